// round 1
// baseline (speedup 1.0000x reference)
#include <cuda_runtime.h>
#include <cuda_bf16.h>

// Problem shape (fixed per reference setup_inputs)
constexpr int Bn = 8;     // batch
constexpr int Tn = 4096;  // xs rows (M)
constexpr int Sn = 256;   // spk rows (N)
constexpr int Dn = 512;   // feature (K)

#define EPS_F 1e-8f

// Scratch for inverse norms (no cudaMalloc allowed)
__device__ float g_invnx[Bn * Tn];   // 32768
__device__ float g_invny[Bn * Sn];   // 2048

// ---------------------------------------------------------------------------
// Kernel 1: warp-per-row inverse L2 norms: inv = 1 / max(||row||, eps)
// ---------------------------------------------------------------------------
__global__ void cos_norm_kernel(const float* __restrict__ x,
                                const float* __restrict__ y) {
    int gwarp = (blockIdx.x * blockDim.x + threadIdx.x) >> 5;
    int lane  = threadIdx.x & 31;

    const int NX = Bn * Tn;      // 32768 x-rows
    const int NY = Bn * Sn;      // 2048  y-rows

    const float* src;
    float* dst;
    if (gwarp < NX) {
        src = x + (size_t)gwarp * Dn;
        dst = &g_invnx[gwarp];
    } else {
        int r = gwarp - NX;
        if (r >= NY) return;
        src = y + (size_t)r * Dn;
        dst = &g_invny[r];
    }

    const float4* v = reinterpret_cast<const float4*>(src);
    float s = 0.0f;
    #pragma unroll
    for (int i = 0; i < Dn / (4 * 32); ++i) {   // 4 float4 per lane
        float4 f = v[lane + 32 * i];
        s += f.x * f.x + f.y * f.y + f.z * f.z + f.w * f.w;
    }
    #pragma unroll
    for (int o = 16; o > 0; o >>= 1)
        s += __shfl_xor_sync(0xffffffffu, s, o);

    if (lane == 0)
        *dst = 1.0f / fmaxf(sqrtf(s), EPS_F);
}

// ---------------------------------------------------------------------------
// Kernel 2: per-batch NT GEMM C[M,N] = X[M,K] * Y[N,K]^T, epilogue scales by
// invnx[row] * invny[col]. 128x128 CTA tile, BK=16, 256 threads, 8x8/thread.
// ---------------------------------------------------------------------------
constexpr int BM = 128, BN = 128, BK = 16;
constexpr int TM = 8, TN = 8;
constexpr int PAD = 4;   // keeps 16B alignment of smem rows, skews banks

__global__ __launch_bounds__(256, 2)
void cos_gemm_kernel(const float* __restrict__ X,
                     const float* __restrict__ Y,
                     float* __restrict__ out) {
    __shared__ float As[BK][BM + PAD];
    __shared__ float Bs[BK][BN + PAD];

    const int b  = blockIdx.z;
    const int m0 = blockIdx.x * BM;
    const int n0 = blockIdx.y * BN;

    const float* A  = X   + (size_t)b * Tn * Dn + (size_t)m0 * Dn;
    const float* Bp = Y   + (size_t)b * Sn * Dn + (size_t)n0 * Dn;
    float*       C  = out + (size_t)b * Tn * Sn + (size_t)m0 * Sn + n0;

    const int tid = threadIdx.x;
    // global->smem loader mapping: 512 float4 per tile, 2 per thread
    const int lr = tid >> 2;          // row 0..63 (and +64)
    const int lk = (tid & 3) * 4;     // k offset 0,4,8,12
    // compute mapping: 16x16 thread grid
    const int tx = tid & 15;          // N direction
    const int ty = tid >> 4;          // M direction

    float acc[TM][TN];
    #pragma unroll
    for (int i = 0; i < TM; ++i)
        #pragma unroll
        for (int j = 0; j < TN; ++j)
            acc[i][j] = 0.0f;

    for (int k0 = 0; k0 < Dn; k0 += BK) {
        #pragma unroll
        for (int h = 0; h < 2; ++h) {
            int r = lr + h * 64;
            float4 fa = *reinterpret_cast<const float4*>(A  + (size_t)r * Dn + k0 + lk);
            As[lk + 0][r] = fa.x;
            As[lk + 1][r] = fa.y;
            As[lk + 2][r] = fa.z;
            As[lk + 3][r] = fa.w;
            float4 fb = *reinterpret_cast<const float4*>(Bp + (size_t)r * Dn + k0 + lk);
            Bs[lk + 0][r] = fb.x;
            Bs[lk + 1][r] = fb.y;
            Bs[lk + 2][r] = fb.z;
            Bs[lk + 3][r] = fb.w;
        }
        __syncthreads();

        #pragma unroll
        for (int k = 0; k < BK; ++k) {
            float a[TM], bb[TN];
            float4 a0 = *reinterpret_cast<const float4*>(&As[k][ty * TM]);
            float4 a1 = *reinterpret_cast<const float4*>(&As[k][ty * TM + 4]);
            a[0]=a0.x; a[1]=a0.y; a[2]=a0.z; a[3]=a0.w;
            a[4]=a1.x; a[5]=a1.y; a[6]=a1.z; a[7]=a1.w;
            float4 b0 = *reinterpret_cast<const float4*>(&Bs[k][tx * TN]);
            float4 b1 = *reinterpret_cast<const float4*>(&Bs[k][tx * TN + 4]);
            bb[0]=b0.x; bb[1]=b0.y; bb[2]=b0.z; bb[3]=b0.w;
            bb[4]=b1.x; bb[5]=b1.y; bb[6]=b1.z; bb[7]=b1.w;

            #pragma unroll
            for (int i = 0; i < TM; ++i)
                #pragma unroll
                for (int j = 0; j < TN; ++j)
                    acc[i][j] = fmaf(a[i], bb[j], acc[i][j]);
        }
        __syncthreads();
    }

    // Epilogue: scale by inverse norms, write float4s
    float invx[TM], invy[TN];
    #pragma unroll
    for (int i = 0; i < TM; ++i)
        invx[i] = g_invnx[b * Tn + m0 + ty * TM + i];
    #pragma unroll
    for (int j = 0; j < TN; ++j)
        invy[j] = g_invny[b * Sn + n0 + tx * TN + j];

    #pragma unroll
    for (int i = 0; i < TM; ++i) {
        float* crow = C + (size_t)(ty * TM + i) * Sn + tx * TN;
        float4 w0, w1;
        w0.x = acc[i][0] * invx[i] * invy[0];
        w0.y = acc[i][1] * invx[i] * invy[1];
        w0.z = acc[i][2] * invx[i] * invy[2];
        w0.w = acc[i][3] * invx[i] * invy[3];
        w1.x = acc[i][4] * invx[i] * invy[4];
        w1.y = acc[i][5] * invx[i] * invy[5];
        w1.z = acc[i][6] * invx[i] * invy[6];
        w1.w = acc[i][7] * invx[i] * invy[7];
        *reinterpret_cast<float4*>(crow)     = w0;
        *reinterpret_cast<float4*>(crow + 4) = w1;
    }
}

extern "C" void kernel_launch(void* const* d_in, const int* in_sizes, int n_in,
                              void* d_out, int out_size) {
    const float* xs  = (const float*)d_in[0];   // (8, 4096, 512)
    const float* spk = (const float*)d_in[1];   // (8, 256, 512)
    float* out = (float*)d_out;                 // (8, 4096, 256)

    // Norm kernel: 1 warp per row; 32768 + 2048 = 34816 warps, 8 warps/block
    {
        int warps = Bn * Tn + Bn * Sn;
        int blocks = (warps + 7) / 8;
        cos_norm_kernel<<<blocks, 256>>>(xs, spk);
    }
    // GEMM: grid (M/128, N/128, B)
    {
        dim3 grid(Tn / BM, Sn / BN, Bn);
        cos_gemm_kernel<<<grid, 256>>>(xs, spk, out);
    }
}

// round 2
// speedup vs baseline: 2.2309x; 2.2309x over previous
#include <cuda_runtime.h>
#include <cuda_bf16.h>
#include <cstdint>

// Problem shape (fixed per reference setup_inputs)
constexpr int Bn = 8;     // batch
constexpr int Tn = 4096;  // xs rows (M)
constexpr int Sn = 256;   // spk rows (N)
constexpr int Dn = 512;   // feature (K)

#define EPS_F 1e-8f

// Scratch for inverse norms (no cudaMalloc allowed)
__device__ float g_invnx[Bn * Tn];   // 32768
__device__ float g_invny[Bn * Sn];   // 2048

// ---------------------------------------------------------------------------
// Kernel 1: warp-per-row inverse L2 norms: inv = 1 / max(||row||, eps)
// ---------------------------------------------------------------------------
__global__ void cos_norm_kernel(const float* __restrict__ x,
                                const float* __restrict__ y) {
    int gwarp = (blockIdx.x * blockDim.x + threadIdx.x) >> 5;
    int lane  = threadIdx.x & 31;

    const int NX = Bn * Tn;      // 32768 x-rows
    const int NY = Bn * Sn;      // 2048  y-rows

    const float* src;
    float* dst;
    if (gwarp < NX) {
        src = x + (size_t)gwarp * Dn;
        dst = &g_invnx[gwarp];
    } else {
        int r = gwarp - NX;
        if (r >= NY) return;
        src = y + (size_t)r * Dn;
        dst = &g_invny[r];
    }

    const float4* v = reinterpret_cast<const float4*>(src);
    float s = 0.0f;
    #pragma unroll
    for (int i = 0; i < Dn / (4 * 32); ++i) {   // 4 float4 per lane
        float4 f = v[lane + 32 * i];
        s += f.x * f.x + f.y * f.y + f.z * f.z + f.w * f.w;
    }
    #pragma unroll
    for (int o = 16; o > 0; o >>= 1)
        s += __shfl_xor_sync(0xffffffffu, s, o);

    if (lane == 0)
        *dst = 1.0f / fmaxf(sqrtf(s), EPS_F);
}

// ---------------------------------------------------------------------------
// Kernel 2: per-batch NT GEMM via TF32 tensor cores.
// C[M,N] = X[M,K] * Y[N,K]^T, epilogue scales by invnx[row]*invny[col].
// CTA tile 128x128, BK=16, 256 threads (8 warps, 4x2), m16n8k8 tf32 mma.
// smem stride 20 floats -> conflict-free fragment LDS pattern (20r+c mod 32).
// ---------------------------------------------------------------------------
constexpr int BM = 128, BN = 128, BK = 16;
constexpr int SSTR = 20;                 // padded smem row stride (floats)
constexpr int NT = Dn / BK;              // 32 k-tiles

__device__ __forceinline__ uint32_t f2tf(float f) {
    uint32_t u;
    asm("cvt.rna.tf32.f32 %0, %1;" : "=r"(u) : "f"(f));
    return u;
}

__device__ __forceinline__ void mma_tf32(float c[4], const uint32_t a[4],
                                         uint32_t b0, uint32_t b1) {
    asm volatile(
        "mma.sync.aligned.m16n8k8.row.col.f32.tf32.tf32.f32 "
        "{%0,%1,%2,%3}, {%4,%5,%6,%7}, {%8,%9}, {%0,%1,%2,%3};"
        : "+f"(c[0]), "+f"(c[1]), "+f"(c[2]), "+f"(c[3])
        : "r"(a[0]), "r"(a[1]), "r"(a[2]), "r"(a[3]), "r"(b0), "r"(b1));
}

__global__ __launch_bounds__(256, 2)
void cos_gemm_tf32(const float* __restrict__ X,
                   const float* __restrict__ Y,
                   float* __restrict__ out) {
    __shared__ uint32_t As[2][BM * SSTR];   // 10240 B each buf
    __shared__ uint32_t Bs[2][BN * SSTR];

    const int tid  = threadIdx.x;
    const int b    = blockIdx.z;
    const int mcta = blockIdx.x * BM;
    const int ncta = blockIdx.y * BN;

    const float* A  = X + (size_t)b * Tn * Dn + (size_t)mcta * Dn;
    const float* Bp = Y + (size_t)b * Sn * Dn + (size_t)ncta * Dn;

    // -------- global load mapping: 4 float4 per thread per k-tile --------
    const int lrow  = tid >> 2;          // 0..63
    const int lquad = (tid & 3) * 4;     // 0,4,8,12 (k offset within tile)
    const float* ga0 = A  + (size_t)lrow * Dn + lquad;
    const float* ga1 = ga0 + (size_t)64 * Dn;
    const float* gb0 = Bp + (size_t)lrow * Dn + lquad;
    const float* gb1 = gb0 + (size_t)64 * Dn;
    const int s0 = lrow * SSTR + lquad;
    const int s1 = (lrow + 64) * SSTR + lquad;

    // -------- compute mapping --------
    const int wid  = tid >> 5;
    const int lane = tid & 31;
    const int wm   = wid >> 1;           // 0..3  (M dir, 32 rows each)
    const int wn   = wid & 1;            // 0..1  (N dir, 64 cols each)
    const int gid  = lane >> 2;          // 0..7
    const int tig  = lane & 3;           // 0..3

    float acc[2][8][4];
    #pragma unroll
    for (int i = 0; i < 2; ++i)
        #pragma unroll
        for (int j = 0; j < 8; ++j)
            #pragma unroll
            for (int q = 0; q < 4; ++q)
                acc[i][j][q] = 0.0f;

    float4 ra0, ra1, rb0, rb1;

    auto LDG = [&](int kt) {
        int ko = kt * BK;
        ra0 = *reinterpret_cast<const float4*>(ga0 + ko);
        ra1 = *reinterpret_cast<const float4*>(ga1 + ko);
        rb0 = *reinterpret_cast<const float4*>(gb0 + ko);
        rb1 = *reinterpret_cast<const float4*>(gb1 + ko);
    };
    auto STS = [&](int buf) {
        uint4 u;
        u.x = f2tf(ra0.x); u.y = f2tf(ra0.y); u.z = f2tf(ra0.z); u.w = f2tf(ra0.w);
        *reinterpret_cast<uint4*>(&As[buf][s0]) = u;
        u.x = f2tf(ra1.x); u.y = f2tf(ra1.y); u.z = f2tf(ra1.z); u.w = f2tf(ra1.w);
        *reinterpret_cast<uint4*>(&As[buf][s1]) = u;
        u.x = f2tf(rb0.x); u.y = f2tf(rb0.y); u.z = f2tf(rb0.z); u.w = f2tf(rb0.w);
        *reinterpret_cast<uint4*>(&Bs[buf][s0]) = u;
        u.x = f2tf(rb1.x); u.y = f2tf(rb1.y); u.z = f2tf(rb1.z); u.w = f2tf(rb1.w);
        *reinterpret_cast<uint4*>(&Bs[buf][s1]) = u;
    };

    LDG(0);
    STS(0);
    __syncthreads();

    #pragma unroll 1
    for (int kt = 0; kt < NT; ++kt) {
        const int cur = kt & 1;
        const bool more = (kt + 1 < NT);
        if (more) LDG(kt + 1);

        const uint32_t* __restrict__ Ab = As[cur];
        const uint32_t* __restrict__ Bb = Bs[cur];

        #pragma unroll
        for (int s = 0; s < 2; ++s) {           // two k=8 steps per tile
            const int kb = s * 8;
            uint32_t a[2][4];
            #pragma unroll
            for (int i = 0; i < 2; ++i) {
                int r0 = wm * 32 + i * 16 + gid;
                a[i][0] = Ab[r0 * SSTR + kb + tig];
                a[i][1] = Ab[(r0 + 8) * SSTR + kb + tig];
                a[i][2] = Ab[r0 * SSTR + kb + tig + 4];
                a[i][3] = Ab[(r0 + 8) * SSTR + kb + tig + 4];
            }
            #pragma unroll
            for (int j = 0; j < 8; ++j) {
                int n0 = wn * 64 + j * 8 + gid;
                uint32_t b0 = Bb[n0 * SSTR + kb + tig];
                uint32_t b1 = Bb[n0 * SSTR + kb + tig + 4];
                mma_tf32(acc[0][j], a[0], b0, b1);
                mma_tf32(acc[1][j], a[1], b0, b1);
            }
        }

        __syncthreads();
        if (more) STS((kt + 1) & 1);
        __syncthreads();
    }

    // -------- epilogue: scale by inverse norms, float2 stores --------
    float* C = out + (size_t)b * Tn * Sn + (size_t)mcta * Sn + ncta;
    const float* invx = &g_invnx[b * Tn + mcta];
    const float* invy = &g_invny[b * Sn + ncta];

    #pragma unroll
    for (int i = 0; i < 2; ++i) {
        const int rA = wm * 32 + i * 16 + gid;
        const float sx0 = invx[rA];
        const float sx1 = invx[rA + 8];
        #pragma unroll
        for (int j = 0; j < 8; ++j) {
            const int c0 = wn * 64 + j * 8 + tig * 2;
            const float sy0 = invy[c0];
            const float sy1 = invy[c0 + 1];
            float2 w;
            w.x = acc[i][j][0] * sx0 * sy0;
            w.y = acc[i][j][1] * sx0 * sy1;
            *reinterpret_cast<float2*>(&C[(size_t)rA * Sn + c0]) = w;
            w.x = acc[i][j][2] * sx1 * sy0;
            w.y = acc[i][j][3] * sx1 * sy1;
            *reinterpret_cast<float2*>(&C[(size_t)(rA + 8) * Sn + c0]) = w;
        }
    }
}

extern "C" void kernel_launch(void* const* d_in, const int* in_sizes, int n_in,
                              void* d_out, int out_size) {
    const float* xs  = (const float*)d_in[0];   // (8, 4096, 512)
    const float* spk = (const float*)d_in[1];   // (8, 256, 512)
    float* out = (float*)d_out;                 // (8, 4096, 256)

    {
        int warps = Bn * Tn + Bn * Sn;
        int blocks = (warps + 7) / 8;
        cos_norm_kernel<<<blocks, 256>>>(xs, spk);
    }
    {
        dim3 grid(Tn / BM, Sn / BN, Bn);
        cos_gemm_tf32<<<grid, 256>>>(xs, spk, out);
    }
}

// round 6
// speedup vs baseline: 2.5729x; 1.1533x over previous
#include <cuda_runtime.h>
#include <cstdint>

// Problem shape (fixed per reference setup_inputs)
constexpr int Bn = 8;     // batch
constexpr int Tn = 4096;  // xs rows (M)
constexpr int Sn = 256;   // spk rows (N)
constexpr int Dn = 512;   // feature (K)

#define EPS_F 1e-8f

// ---------------------------------------------------------------------------
// Fused kernel: per-batch NT GEMM via TF32 mma.sync + in-register row norms.
// C[M,N] = (X/||X||)[M,K] * (Y/||Y||)[N,K]^T
// CTA tile 128x128, BK=16, 256 threads (8 warps, 4x2), m16n8k8 tf32 mma.
// smem row-major stride 20 floats -> conflict-free fragment LDS pattern.
// One __syncthreads per k-tile; norms fused into the producer path.
// ---------------------------------------------------------------------------
constexpr int BM = 128, BN = 128, BK = 16;
constexpr int SSTR = 20;                 // padded smem row stride (floats)
constexpr int NT = Dn / BK;              // 32 k-tiles

__device__ __forceinline__ uint32_t f2tf(float f) {
    uint32_t u;
    asm("cvt.rna.tf32.f32 %0, %1;" : "=r"(u) : "f"(f));
    return u;
}

__device__ __forceinline__ void mma_tf32(float c[4], const uint32_t a[4],
                                         uint32_t b0, uint32_t b1) {
    asm volatile(
        "mma.sync.aligned.m16n8k8.row.col.f32.tf32.tf32.f32 "
        "{%0,%1,%2,%3}, {%4,%5,%6,%7}, {%8,%9}, {%0,%1,%2,%3};"
        : "+f"(c[0]), "+f"(c[1]), "+f"(c[2]), "+f"(c[3])
        : "r"(a[0]), "r"(a[1]), "r"(a[2]), "r"(a[3]), "r"(b0), "r"(b1));
}

__device__ __forceinline__ float dot4(float4 v) {
    return v.x * v.x + v.y * v.y + v.z * v.z + v.w * v.w;
}

__global__ __launch_bounds__(256, 2)
void cos_gemm_fused(const float* __restrict__ X,
                    const float* __restrict__ Y,
                    float* __restrict__ out) {
    __shared__ uint32_t As[2][BM * SSTR];   // 10240 B each buf
    __shared__ uint32_t Bs[2][BN * SSTR];
    __shared__ float sinvx[BM];
    __shared__ float sinvy[BN];

    const int tid  = threadIdx.x;
    const int b    = blockIdx.z;
    const int mcta = blockIdx.x * BM;
    const int ncta = blockIdx.y * BN;

    const float* A  = X + (size_t)b * Tn * Dn + (size_t)mcta * Dn;
    const float* Bp = Y + (size_t)b * Sn * Dn + (size_t)ncta * Dn;

    // -------- global load mapping: 4 float4 per thread per k-tile --------
    const int lrow  = tid >> 2;          // 0..63
    const int lquad = (tid & 3) * 4;     // 0,4,8,12 (k offset within tile)
    const float* ga0 = A  + (size_t)lrow * Dn + lquad;
    const float* ga1 = ga0 + (size_t)64 * Dn;
    const float* gb0 = Bp + (size_t)lrow * Dn + lquad;
    const float* gb1 = gb0 + (size_t)64 * Dn;
    const int s0 = lrow * SSTR + lquad;
    const int s1 = (lrow + 64) * SSTR + lquad;

    // -------- compute mapping --------
    const int wid  = tid >> 5;
    const int lane = tid & 31;
    const int wm   = wid >> 1;           // 0..3  (M dir, 32 rows each)
    const int wn   = wid & 1;            // 0..1  (N dir, 64 cols each)
    const int gid  = lane >> 2;          // 0..7
    const int tig  = lane & 3;           // 0..3

    float acc[2][8][4];
    #pragma unroll
    for (int i = 0; i < 2; ++i)
        #pragma unroll
        for (int j = 0; j < 8; ++j)
            #pragma unroll
            for (int q = 0; q < 4; ++q)
                acc[i][j][q] = 0.0f;

    // norm partials for this thread's fixed rows (lrow, lrow+64) of A and B
    float nx0 = 0.0f, nx1 = 0.0f, ny0 = 0.0f, ny1 = 0.0f;

    float4 ra0, ra1, rb0, rb1;

    auto LDG = [&](int kt) {
        int ko = kt * BK;
        ra0 = *reinterpret_cast<const float4*>(ga0 + ko);
        ra1 = *reinterpret_cast<const float4*>(ga1 + ko);
        rb0 = *reinterpret_cast<const float4*>(gb0 + ko);
        rb1 = *reinterpret_cast<const float4*>(gb1 + ko);
    };
    // STS + fused fp32 norm accumulation on the staged registers
    auto STSN = [&](int buf) {
        nx0 += dot4(ra0);
        nx1 += dot4(ra1);
        ny0 += dot4(rb0);
        ny1 += dot4(rb1);
        uint4 u;
        u.x = f2tf(ra0.x); u.y = f2tf(ra0.y); u.z = f2tf(ra0.z); u.w = f2tf(ra0.w);
        *reinterpret_cast<uint4*>(&As[buf][s0]) = u;
        u.x = f2tf(ra1.x); u.y = f2tf(ra1.y); u.z = f2tf(ra1.z); u.w = f2tf(ra1.w);
        *reinterpret_cast<uint4*>(&As[buf][s1]) = u;
        u.x = f2tf(rb0.x); u.y = f2tf(rb0.y); u.z = f2tf(rb0.z); u.w = f2tf(rb0.w);
        *reinterpret_cast<uint4*>(&Bs[buf][s0]) = u;
        u.x = f2tf(rb1.x); u.y = f2tf(rb1.y); u.z = f2tf(rb1.z); u.w = f2tf(rb1.w);
        *reinterpret_cast<uint4*>(&Bs[buf][s1]) = u;
    };

    LDG(0);
    STSN(0);
    __syncthreads();

    #pragma unroll 1
    for (int kt = 0; kt < NT; ++kt) {
        const int cur = kt & 1;
        const bool more = (kt + 1 < NT);

        // LDG for next tile first: L2 latency drains under the mma block.
        if (more) LDG(kt + 1);

        const uint32_t* __restrict__ Ab = As[cur];
        const uint32_t* __restrict__ Bb = Bs[cur];

        #pragma unroll
        for (int s = 0; s < 2; ++s) {           // two k=8 steps per tile
            const int kb = s * 8;
            uint32_t a[2][4];
            #pragma unroll
            for (int i = 0; i < 2; ++i) {
                int r0 = wm * 32 + i * 16 + gid;
                a[i][0] = Ab[r0 * SSTR + kb + tig];
                a[i][1] = Ab[(r0 + 8) * SSTR + kb + tig];
                a[i][2] = Ab[r0 * SSTR + kb + tig + 4];
                a[i][3] = Ab[(r0 + 8) * SSTR + kb + tig + 4];
            }
            #pragma unroll
            for (int j = 0; j < 8; ++j) {
                int n0 = wn * 64 + j * 8 + gid;
                uint32_t b0 = Bb[n0 * SSTR + kb + tig];
                uint32_t b1 = Bb[n0 * SSTR + kb + tig + 4];
                mma_tf32(acc[0][j], a[0], b0, b1);
                mma_tf32(acc[1][j], a[1], b0, b1);
            }
        }

        // STS into the *other* buffer; everyone finished reading it before
        // the previous sync, so one barrier per tile is sufficient.
        if (more) STSN((kt + 1) & 1);
        __syncthreads();
    }

    // -------- finish norms: reduce across the 4 k-quad threads per row ----
    // threads tid = 4*lrow + c (c = tid&3) are contiguous lanes in one warp.
    nx0 += __shfl_xor_sync(0xffffffffu, nx0, 1);
    nx0 += __shfl_xor_sync(0xffffffffu, nx0, 2);
    nx1 += __shfl_xor_sync(0xffffffffu, nx1, 1);
    nx1 += __shfl_xor_sync(0xffffffffu, nx1, 2);
    ny0 += __shfl_xor_sync(0xffffffffu, ny0, 1);
    ny0 += __shfl_xor_sync(0xffffffffu, ny0, 2);
    ny1 += __shfl_xor_sync(0xffffffffu, ny1, 1);
    ny1 += __shfl_xor_sync(0xffffffffu, ny1, 2);
    if ((tid & 3) == 0) {
        sinvx[lrow]      = 1.0f / fmaxf(sqrtf(nx0), EPS_F);
        sinvx[lrow + 64] = 1.0f / fmaxf(sqrtf(nx1), EPS_F);
        sinvy[lrow]      = 1.0f / fmaxf(sqrtf(ny0), EPS_F);
        sinvy[lrow + 64] = 1.0f / fmaxf(sqrtf(ny1), EPS_F);
    }
    __syncthreads();

    // -------- epilogue: scale by inverse norms, float2 stores --------
    float* C = out + (size_t)b * Tn * Sn + (size_t)mcta * Sn + ncta;

    #pragma unroll
    for (int i = 0; i < 2; ++i) {
        const int rA = wm * 32 + i * 16 + gid;
        const float sx0 = sinvx[rA];
        const float sx1 = sinvx[rA + 8];
        #pragma unroll
        for (int j = 0; j < 8; ++j) {
            const int c0 = wn * 64 + j * 8 + tig * 2;
            const float sy0 = sinvy[c0];
            const float sy1 = sinvy[c0 + 1];
            float2 w;
            w.x = acc[i][j][0] * sx0 * sy0;
            w.y = acc[i][j][1] * sx0 * sy1;
            *reinterpret_cast<float2*>(&C[(size_t)rA * Sn + c0]) = w;
            w.x = acc[i][j][2] * sx1 * sy0;
            w.y = acc[i][j][3] * sx1 * sy1;
            *reinterpret_cast<float2*>(&C[(size_t)(rA + 8) * Sn + c0]) = w;
        }
    }
}

extern "C" void kernel_launch(void* const* d_in, const int* in_sizes, int n_in,
                              void* d_out, int out_size) {
    const float* xs  = (const float*)d_in[0];   // (8, 4096, 512)
    const float* spk = (const float*)d_in[1];   // (8, 256, 512)
    float* out = (float*)d_out;                 // (8, 4096, 256)

    dim3 grid(Tn / BM, Sn / BN, Bn);            // (32, 2, 8) = 512 CTAs
    cos_gemm_fused<<<grid, 256>>>(xs, spk, out);
}

// round 8
// speedup vs baseline: 2.8189x; 1.0956x over previous
#include <cuda_runtime.h>
#include <cstdint>

// Problem shape (fixed per reference setup_inputs)
constexpr int Bn = 8;     // batch
constexpr int Tn = 4096;  // xs rows (M)
constexpr int Sn = 256;   // spk rows (N)
constexpr int Dn = 512;   // feature (K)

#define EPS_F 1e-8f

// ---------------------------------------------------------------------------
// Fused kernel: per-batch NT GEMM via TF32 mma.sync + in-register row norms.
// CTA tile 128x128, BK=32, 256 threads (8 warps, 4x2), m16n8k8 tf32 mma.
// Dynamic smem, stride-36 rows -> conflict-free STS.128 and fragment LDS.
// One __syncthreads per k-tile (16 tiles).
// ---------------------------------------------------------------------------
constexpr int BM = 128, BN = 128, BK = 32;
constexpr int SSTR = 36;                 // padded smem row stride (uint32)
constexpr int NT = Dn / BK;              // 16 k-tiles
constexpr int TILE_U32 = BM * SSTR;      // 4608 uint32 per tile buffer

// dynamic smem layout (bytes)
constexpr int SM_A    = 0;                       // uint32[2][TILE_U32]
constexpr int SM_B    = 2 * TILE_U32 * 4;        // 36864
constexpr int SM_INVX = 4 * TILE_U32 * 4;        // 73728 (128 floats)
constexpr int SM_INVY = SM_INVX + BM * 4;        // 74240 (128 floats)
constexpr int SMEM_TOTAL = SM_INVY + BN * 4;     // 74752

__device__ __forceinline__ uint32_t f2tf(float f) {
    uint32_t u;
    asm("cvt.rna.tf32.f32 %0, %1;" : "=r"(u) : "f"(f));
    return u;
}

__device__ __forceinline__ void mma_tf32(float c[4], const uint32_t a[4],
                                         uint32_t b0, uint32_t b1) {
    asm volatile(
        "mma.sync.aligned.m16n8k8.row.col.f32.tf32.tf32.f32 "
        "{%0,%1,%2,%3}, {%4,%5,%6,%7}, {%8,%9}, {%0,%1,%2,%3};"
        : "+f"(c[0]), "+f"(c[1]), "+f"(c[2]), "+f"(c[3])
        : "r"(a[0]), "r"(a[1]), "r"(a[2]), "r"(a[3]), "r"(b0), "r"(b1));
}

__device__ __forceinline__ float dot4(float4 v) {
    return v.x * v.x + v.y * v.y + v.z * v.z + v.w * v.w;
}

__global__ __launch_bounds__(256, 2)
void cos_gemm_fused32(const float* __restrict__ X,
                      const float* __restrict__ Y,
                      float* __restrict__ out) {
    extern __shared__ char smraw[];
    uint32_t* As    = reinterpret_cast<uint32_t*>(smraw + SM_A);   // [2][TILE_U32]
    uint32_t* Bs    = reinterpret_cast<uint32_t*>(smraw + SM_B);
    float*    sinvx = reinterpret_cast<float*>(smraw + SM_INVX);
    float*    sinvy = reinterpret_cast<float*>(smraw + SM_INVY);

    const int tid  = threadIdx.x;
    const int b    = blockIdx.z;
    const int mcta = blockIdx.x * BM;
    const int ncta = blockIdx.y * BN;

    const float* A  = X + (size_t)b * Tn * Dn + (size_t)mcta * Dn;
    const float* Bp = Y + (size_t)b * Sn * Dn + (size_t)ncta * Dn;

    // -------- producer mapping: 8 float4 per thread per k-tile ------------
    // thread -> (base row lrow 0..31, k-quad lq in 0..28 step 4); rows +32p
    const int lrow = tid >> 3;
    const int lq   = (tid & 7) * 4;
    const float* gA = A  + (size_t)lrow * Dn + lq;
    const float* gB = Bp + (size_t)lrow * Dn + lq;
    int soff[4];
    #pragma unroll
    for (int p = 0; p < 4; ++p)
        soff[p] = (lrow + 32 * p) * SSTR + lq;

    // -------- compute mapping --------
    const int wid  = tid >> 5;
    const int lane = tid & 31;
    const int wm   = wid >> 1;           // 0..3  (M dir, 32 rows each)
    const int wn   = wid & 1;            // 0..1  (N dir, 64 cols each)
    const int gid  = lane >> 2;          // 0..7
    const int tig  = lane & 3;           // 0..3

    float acc[2][8][4];
    #pragma unroll
    for (int i = 0; i < 2; ++i)
        #pragma unroll
        for (int j = 0; j < 8; ++j)
            #pragma unroll
            for (int q = 0; q < 4; ++q)
                acc[i][j][q] = 0.0f;

    // norm partials for this thread's 4 A rows and 4 B rows
    float nx[4] = {0, 0, 0, 0}, ny[4] = {0, 0, 0, 0};

    float4 ra[4], rb[4];

    auto LDG = [&](int kt) {
        const int ko = kt * BK;
        #pragma unroll
        for (int p = 0; p < 4; ++p) {
            ra[p] = *reinterpret_cast<const float4*>(gA + (size_t)(32 * p) * Dn + ko);
            rb[p] = *reinterpret_cast<const float4*>(gB + (size_t)(32 * p) * Dn + ko);
        }
    };
    // STS + fused fp32 norm accumulation on staged registers
    auto STSN = [&](int buf) {
        uint32_t* Ad = As + buf * TILE_U32;
        uint32_t* Bd = Bs + buf * TILE_U32;
        #pragma unroll
        for (int p = 0; p < 4; ++p) {
            float4 v = ra[p];
            nx[p] += dot4(v);
            uint4 u;
            u.x = f2tf(v.x); u.y = f2tf(v.y); u.z = f2tf(v.z); u.w = f2tf(v.w);
            *reinterpret_cast<uint4*>(&Ad[soff[p]]) = u;
            v = rb[p];
            ny[p] += dot4(v);
            u.x = f2tf(v.x); u.y = f2tf(v.y); u.z = f2tf(v.z); u.w = f2tf(v.w);
            *reinterpret_cast<uint4*>(&Bd[soff[p]]) = u;
        }
    };

    LDG(0);
    STSN(0);
    __syncthreads();

    #pragma unroll 1
    for (int kt = 0; kt < NT; ++kt) {
        const int cur = kt & 1;
        const bool more = (kt + 1 < NT);

        // prefetch next tile to registers; drains under the 64-mma block
        if (more) LDG(kt + 1);

        const uint32_t* __restrict__ Ab = As + cur * TILE_U32;
        const uint32_t* __restrict__ Bb = Bs + cur * TILE_U32;

        #pragma unroll
        for (int s = 0; s < 4; ++s) {           // four k=8 steps per tile
            const int kb = s * 8;
            uint32_t a[2][4];
            #pragma unroll
            for (int i = 0; i < 2; ++i) {
                int r0 = wm * 32 + i * 16 + gid;
                a[i][0] = Ab[r0 * SSTR + kb + tig];
                a[i][1] = Ab[(r0 + 8) * SSTR + kb + tig];
                a[i][2] = Ab[r0 * SSTR + kb + tig + 4];
                a[i][3] = Ab[(r0 + 8) * SSTR + kb + tig + 4];
            }
            #pragma unroll
            for (int j = 0; j < 8; ++j) {
                int n0 = wn * 64 + j * 8 + gid;
                uint32_t b0 = Bb[n0 * SSTR + kb + tig];
                uint32_t b1 = Bb[n0 * SSTR + kb + tig + 4];
                mma_tf32(acc[0][j], a[0], b0, b1);
                mma_tf32(acc[1][j], a[1], b0, b1);
            }
        }

        // store into the buffer everyone stopped reading before prev sync
        if (more) STSN((kt + 1) & 1);
        __syncthreads();
    }

    // -------- finish norms: reduce across the 8 k-quad threads per row ----
    // threads tid = 8*lrow + c (c = tid&7) are contiguous lanes in one warp.
    #pragma unroll
    for (int p = 0; p < 4; ++p) {
        float s = nx[p];
        s += __shfl_xor_sync(0xffffffffu, s, 1);
        s += __shfl_xor_sync(0xffffffffu, s, 2);
        s += __shfl_xor_sync(0xffffffffu, s, 4);
        float t = ny[p];
        t += __shfl_xor_sync(0xffffffffu, t, 1);
        t += __shfl_xor_sync(0xffffffffu, t, 2);
        t += __shfl_xor_sync(0xffffffffu, t, 4);
        if ((tid & 7) == 0) {
            sinvx[lrow + 32 * p] = 1.0f / fmaxf(sqrtf(s), EPS_F);
            sinvy[lrow + 32 * p] = 1.0f / fmaxf(sqrtf(t), EPS_F);
        }
    }
    __syncthreads();

    // -------- epilogue: scale by inverse norms, float2 stores --------
    float* C = out + (size_t)b * Tn * Sn + (size_t)mcta * Sn + ncta;

    #pragma unroll
    for (int i = 0; i < 2; ++i) {
        const int rA = wm * 32 + i * 16 + gid;
        const float sx0 = sinvx[rA];
        const float sx1 = sinvx[rA + 8];
        #pragma unroll
        for (int j = 0; j < 8; ++j) {
            const int c0 = wn * 64 + j * 8 + tig * 2;
            const float sy0 = sinvy[c0];
            const float sy1 = sinvy[c0 + 1];
            float2 w;
            w.x = acc[i][j][0] * sx0 * sy0;
            w.y = acc[i][j][1] * sx0 * sy1;
            *reinterpret_cast<float2*>(&C[(size_t)rA * Sn + c0]) = w;
            w.x = acc[i][j][2] * sx1 * sy0;
            w.y = acc[i][j][3] * sx1 * sy1;
            *reinterpret_cast<float2*>(&C[(size_t)(rA + 8) * Sn + c0]) = w;
        }
    }
}

extern "C" void kernel_launch(void* const* d_in, const int* in_sizes, int n_in,
                              void* d_out, int out_size) {
    const float* xs  = (const float*)d_in[0];   // (8, 4096, 512)
    const float* spk = (const float*)d_in[1];   // (8, 256, 512)
    float* out = (float*)d_out;                 // (8, 4096, 256)

    static bool attr_set = false;
    if (!attr_set) {
        cudaFuncSetAttribute(cos_gemm_fused32,
                             cudaFuncAttributeMaxDynamicSharedMemorySize,
                             SMEM_TOTAL);
        attr_set = true;
    }

    dim3 grid(Tn / BM, Sn / BN, Bn);            // (32, 2, 8) = 512 CTAs
    cos_gemm_fused32<<<grid, 256, SMEM_TOTAL>>>(xs, spk, out);
}